// round 2
// baseline (speedup 1.0000x reference)
#include <cuda_runtime.h>

#define TSTEPS 2048
#define BATCH  32
#define IDIM   512
#define HDIM   512
#define GDIM   2048   // 4*H

#define RG     128    // persistent CTAs in recurrence kernel
#define RROWS  16     // gate rows per CTA (128*16 = 2048)
#define HSTRIDE 516   // padded h row stride in smem (floats)
#define NBAR   (1 + 2 * TSTEPS)

// ---- scratch (static device allocations; no cudaMalloc allowed) ----
__device__ float g_xpre[(size_t)TSTEPS * GDIM * BATCH];   // 512 MB
__device__ float g_gates[GDIM * BATCH];                   // activated gates
__device__ float g_h[BATCH * HDIM];                       // recurrent h
__device__ unsigned long long g_cnt;                      // grid barrier counter

// ============================================================
// Phase 1: x_pre[t][g][b] = (bi[g]+bh[g]) + sum_i Wi[g][i]*x[t][b][i]
// Tile: 128 g x 32 b per CTA, K chunks of 32.
// ============================================================
__global__ void __launch_bounds__(256) p1_gemm(
    const float* __restrict__ x, const float* __restrict__ Wi,
    const float* __restrict__ bi, const float* __restrict__ bh)
{
    __shared__ __align__(16) float wt[128 * 33];  // [g][kc] pad 33
    __shared__ __align__(16) float xt[32 * 36];   // [kc][b] pad 36

    const int t     = blockIdx.y;
    const int gbase = blockIdx.x * 128;
    const int tid   = threadIdx.x;
    const int tx    = tid & 7;    // b group (4 b each)
    const int ty    = tid >> 3;   // g group (4 g each)

    float acc[4][4];
    #pragma unroll
    for (int i = 0; i < 4; i++)
        #pragma unroll
        for (int j = 0; j < 4; j++) acc[i][j] = 0.f;

    const float* xrow = x + (size_t)t * BATCH * IDIM;

    for (int kb = 0; kb < IDIM; kb += 32) {
        __syncthreads();
        // Wi tile: 128 rows x 32 cols (1024 float4, 4 per thread)
        #pragma unroll
        for (int r = 0; r < 4; r++) {
            int lin  = r * 256 + tid;
            int grow = lin >> 3;
            int c4   = lin & 7;
            float4 v = *(const float4*)(Wi + (size_t)(gbase + grow) * IDIM + kb + c4 * 4);
            float* d = &wt[grow * 33 + c4 * 4];
            d[0] = v.x; d[1] = v.y; d[2] = v.z; d[3] = v.w;
        }
        // x tile, transposed to [kc][b]
        {
            int b  = tid >> 3;
            int c4 = tid & 7;
            float4 v = *(const float4*)(xrow + (size_t)b * IDIM + kb + c4 * 4);
            xt[(c4 * 4 + 0) * 36 + b] = v.x;
            xt[(c4 * 4 + 1) * 36 + b] = v.y;
            xt[(c4 * 4 + 2) * 36 + b] = v.z;
            xt[(c4 * 4 + 3) * 36 + b] = v.w;
        }
        __syncthreads();
        #pragma unroll 4
        for (int kc = 0; kc < 32; kc++) {
            float4 xv = *(const float4*)(&xt[kc * 36 + tx * 4]);
            float w0 = wt[(ty * 4 + 0) * 33 + kc];
            float w1 = wt[(ty * 4 + 1) * 33 + kc];
            float w2 = wt[(ty * 4 + 2) * 33 + kc];
            float w3 = wt[(ty * 4 + 3) * 33 + kc];
            acc[0][0] += w0 * xv.x; acc[0][1] += w0 * xv.y; acc[0][2] += w0 * xv.z; acc[0][3] += w0 * xv.w;
            acc[1][0] += w1 * xv.x; acc[1][1] += w1 * xv.y; acc[1][2] += w1 * xv.z; acc[1][3] += w1 * xv.w;
            acc[2][0] += w2 * xv.x; acc[2][1] += w2 * xv.y; acc[2][2] += w2 * xv.z; acc[2][3] += w2 * xv.w;
            acc[3][0] += w3 * xv.x; acc[3][1] += w3 * xv.y; acc[3][2] += w3 * xv.z; acc[3][3] += w3 * xv.w;
        }
    }

    float* outp = g_xpre + (size_t)t * GDIM * BATCH;
    #pragma unroll
    for (int i = 0; i < 4; i++) {
        int g = gbase + ty * 4 + i;
        float bb = bi[g] + bh[g];
        float4 v = make_float4(acc[i][0] + bb, acc[i][1] + bb, acc[i][2] + bb, acc[i][3] + bb);
        *(float4*)(outp + (size_t)g * BATCH + tx * 4) = v;
    }
}

// ============================================================
// Grid barrier: monotone u64 counter, run-base via floor division
// (graph-replay safe: each run adds exactly NBAR*RG, never reset).
// ============================================================
__device__ __forceinline__ void gbar(unsigned long long base, int bar)
{
    if (threadIdx.x == 0) {
        __threadfence();
        atomicAdd(&g_cnt, 1ULL);
        unsigned long long target = base + (unsigned long long)bar * RG;
        volatile unsigned long long* vc = &g_cnt;
        while (*vc < target) __nanosleep(64);
        __threadfence();
    }
    __syncthreads();
}

// ============================================================
// Phase 2: persistent recurrence. Each CTA owns 16 Wh rows (smem)
// and 4 h-columns for the cell update (c in registers).
// ============================================================
extern __shared__ __align__(16) float smem_rec[];

__global__ void __launch_bounds__(256) lstm_rec(
    const float* __restrict__ Wh, float* __restrict__ out)
{
    float* ws = smem_rec;                    // 16*512
    float* hs = smem_rec + RROWS * HDIM;     // 32*516 (padded)

    const int tid   = threadIdx.x;
    const int cta   = blockIdx.x;
    const int gbase = cta * RROWS;

    // Load Wh slice once (2048 float4, 8 per thread)
    #pragma unroll
    for (int r = 0; r < 8; r++) {
        int f4 = r * 256 + tid;
        *(float4*)(ws + f4 * 4) = *(const float4*)(Wh + (size_t)gbase * HDIM + (size_t)f4 * 4);
    }

    // cell-update ownership: threads 0..127 own (j = cta*4 + tid/32, b = tid%32)
    const int ub = tid & 31;
    const int uj = cta * 4 + (tid >> 5);
    float creg = 0.f;
    if (tid < 128) g_h[ub * HDIM + uj] = 0.f;

    __shared__ unsigned long long sbase;
    if (tid == 0) {
        unsigned long long v = *(volatile unsigned long long*)&g_cnt;
        unsigned long long per = (unsigned long long)NBAR * RG;
        sbase = (v / per) * per;
    }
    __syncthreads();
    const unsigned long long base = sbase;
    int bar = 0;
    gbar(base, ++bar);   // h initialized everywhere

    const int warp = tid >> 5, lane = tid & 31;
    const float4* w0p = (const float4*)(ws + (2 * warp) * HDIM);
    const float4* w1p = (const float4*)(ws + (2 * warp + 1) * HDIM);
    const int gg0 = gbase + 2 * warp;
    const int gg1 = gg0 + 1;

    for (int t = 0; t < TSTEPS; t++) {
        // Stage h (L2-coherent loads; L1 is stale across SMs)
        #pragma unroll
        for (int r = 0; r < 16; r++) {
            int f4 = r * 256 + tid;
            int b  = f4 >> 7;
            int c4 = f4 & 127;
            float4 v = __ldcg(((const float4*)g_h) + f4);
            *(float4*)(hs + b * HSTRIDE + c4 * 4) = v;
        }
        __syncthreads();

        // Per warp: 2 gate rows x 32 batches; lane = b
        const float4* hp = (const float4*)(hs + lane * HSTRIDE);
        float acc0 = 0.f, acc1 = 0.f;
        #pragma unroll 4
        for (int k = 0; k < 128; k++) {
            float4 hv = hp[k];
            float4 wa = w0p[k];
            float4 wb = w1p[k];
            acc0 += hv.x * wa.x; acc0 += hv.y * wa.y;
            acc0 += hv.z * wa.z; acc0 += hv.w * wa.w;
            acc1 += hv.x * wb.x; acc1 += hv.y * wb.y;
            acc1 += hv.z * wb.z; acc1 += hv.w * wb.w;
        }
        const float* xp = g_xpre + (size_t)t * GDIM * BATCH;
        float p0 = acc0 + xp[gg0 * BATCH + lane];
        float p1 = acc1 + xp[gg1 * BATCH + lane];
        float a0 = (gg0 < 3 * HDIM) ? (1.f / (1.f + __expf(-p0))) : tanhf(p0);
        float a1 = (gg1 < 3 * HDIM) ? (1.f / (1.f + __expf(-p1))) : tanhf(p1);
        g_gates[gg0 * BATCH + lane] = a0;
        g_gates[gg1 * BATCH + lane] = a1;

        gbar(base, ++bar);   // gates ready (fence inside, before arrive)

        if (tid < 128) {
            float ig = __ldcg(&g_gates[(0 * HDIM + uj) * BATCH + ub]);
            float fg = __ldcg(&g_gates[(1 * HDIM + uj) * BATCH + ub]);
            float og = __ldcg(&g_gates[(2 * HDIM + uj) * BATCH + ub]);
            float gt = __ldcg(&g_gates[(3 * HDIM + uj) * BATCH + ub]);
            creg = creg * fg + ig * gt;
            float hn = og * tanhf(creg);
            g_h[ub * HDIM + uj] = hn;
            out[(size_t)t * BATCH * HDIM + ub * HDIM + uj] = hn;
            if (t == TSTEPS - 1) {
                size_t o2 = (size_t)TSTEPS * BATCH * HDIM;
                out[o2 + ub * HDIM + uj] = hn;
                out[o2 + BATCH * HDIM + ub * HDIM + uj] = creg;
            }
        }

        gbar(base, ++bar);   // h ready for next step
    }
}

// ============================================================
extern "C" void kernel_launch(void* const* d_in, const int* in_sizes, int n_in,
                              void* d_out, int out_size)
{
    const float* x  = (const float*)d_in[0];
    const float* Wi = (const float*)d_in[1];
    const float* bi = (const float*)d_in[2];
    const float* Wh = (const float*)d_in[3];
    const float* bh = (const float*)d_in[4];
    float* out = (float*)d_out;

    size_t rec_smem = (size_t)(RROWS * HDIM + BATCH * HSTRIDE) * sizeof(float); // 98816 B
    cudaFuncSetAttribute(lstm_rec, cudaFuncAttributeMaxDynamicSharedMemorySize,
                         (int)rec_smem);

    dim3 g1(GDIM / 128, TSTEPS);
    p1_gemm<<<g1, 256>>>(x, Wi, bi, bh);
    lstm_rec<<<RG, 256, rec_smem>>>(Wh, out);
}

// round 3
// speedup vs baseline: 1.2237x; 1.2237x over previous
#include <cuda_runtime.h>

#define TSTEPS 2048
#define BATCH  32
#define IDIM   512
#define HDIM   512
#define GDIM   2048   // 4*H

#define RG      128    // persistent CTAs in recurrence
#define HSTRIDE 516    // padded h row stride in smem (floats)
#define NBAR    (1 + TSTEPS)

// ---- static device scratch (no cudaMalloc allowed) ----
__device__ float g_xpre[(size_t)TSTEPS * GDIM * BATCH];   // [t][g][b]
__device__ float g_h[2][BATCH * HDIM];                    // double-buffered h
__device__ unsigned long long g_cnt;                      // grid barrier counter

// ---- packed fp32x2 helpers ----
__device__ __forceinline__ unsigned long long fma2(
    unsigned long long a, unsigned long long b, unsigned long long c)
{
    unsigned long long d;
    asm("fma.rn.f32x2 %0, %1, %2, %3;" : "=l"(d) : "l"(a), "l"(b), "l"(c));
    return d;
}
__device__ __forceinline__ float hsum2(unsigned long long p)
{
    float lo, hi;
    asm("mov.b64 {%0, %1}, %2;" : "=f"(lo), "=f"(hi) : "l"(p));
    return lo + hi;
}

// ============================================================
// Phase 1: x_pre[t][g][b] = (bi[g]+bh[g]) + sum_i Wi[g][i]*x[t][b][i]
// CTA tile: 128 g x 32 b (one t). f32x2 inner product.
// ============================================================
__global__ void __launch_bounds__(256) p1_gemm(
    const float* __restrict__ x, const float* __restrict__ Wi,
    const float* __restrict__ bi, const float* __restrict__ bh)
{
    __shared__ __align__(16) float wt[128 * 32];  // [g][k] no pad (broadcast reads)
    __shared__ __align__(16) float xt[32 * 32];   // [b][k], XOR-swizzled chunks

    const int t     = blockIdx.y;
    const int gbase = blockIdx.x * 128;
    const int tid   = threadIdx.x;
    const int tx    = tid & 7;    // picks b set {tx, tx+8, tx+16, tx+24}
    const int ty    = tid >> 3;   // picks g set {4ty .. 4ty+3}

    unsigned long long acc[4][4];
    #pragma unroll
    for (int i = 0; i < 4; i++)
        #pragma unroll
        for (int j = 0; j < 4; j++) acc[i][j] = 0ULL;

    const float* xrow = x + (size_t)t * BATCH * IDIM;
    const int sb = tid >> 3;   // staging: b row
    const int sc = tid & 7;    // staging: chunk

    ulonglong2*       xt2 = (ulonglong2*)xt;
    ulonglong2*       wt2 = (ulonglong2*)wt;

    for (int kb = 0; kb < IDIM; kb += 32) {
        __syncthreads();
        // Wi tile: 128 rows x 32 cols = 1024 float4; 4 per thread
        #pragma unroll
        for (int r = 0; r < 4; r++) {
            int idx = r * 256 + tid;
            int g   = idx >> 3;
            int c   = idx & 7;
            float4 v = *(const float4*)(Wi + (size_t)(gbase + g) * IDIM + kb + c * 4);
            *(float4*)(wt + (g * 8 + c) * 4) = v;
        }
        // x tile [b][k] with chunk swizzle c' = c ^ (b&7)
        {
            float4 v = *(const float4*)(xrow + (size_t)sb * IDIM + kb + sc * 4);
            *(float4*)(xt + (sb * 8 + (sc ^ (sb & 7))) * 4) = v;
        }
        __syncthreads();

        #pragma unroll
        for (int c = 0; c < 8; c++) {
            ulonglong2 xv[4], wv[4];
            #pragma unroll
            for (int j = 0; j < 4; j++) {
                int b = tx + 8 * j;
                xv[j] = xt2[b * 8 + (c ^ tx)];
            }
            #pragma unroll
            for (int i = 0; i < 4; i++)
                wv[i] = wt2[(ty * 4 + i) * 8 + c];
            #pragma unroll
            for (int i = 0; i < 4; i++)
                #pragma unroll
                for (int j = 0; j < 4; j++) {
                    acc[i][j] = fma2(wv[i].x, xv[j].x, acc[i][j]);
                    acc[i][j] = fma2(wv[i].y, xv[j].y, acc[i][j]);
                }
        }
    }

    float* outp = g_xpre + (size_t)t * GDIM * BATCH;
    #pragma unroll
    for (int i = 0; i < 4; i++) {
        int g = gbase + ty * 4 + i;
        float bb = __ldg(bi + g) + __ldg(bh + g);
        #pragma unroll
        for (int j = 0; j < 4; j++) {
            int b = tx + 8 * j;
            outp[(size_t)g * BATCH + b] = hsum2(acc[i][j]) + bb;
        }
    }
}

// ============================================================
// Grid barrier: monotone u64 counter (graph-replay safe)
// ============================================================
__device__ __forceinline__ void gbar(unsigned long long base, int bar)
{
    __syncthreads();
    if (threadIdx.x == 0) {
        __threadfence();
        atomicAdd(&g_cnt, 1ULL);
        unsigned long long target = base + (unsigned long long)bar * RG;
        volatile unsigned long long* vc = &g_cnt;
        while (*vc < target) __nanosleep(32);
        __threadfence();
    }
    __syncthreads();
}

// ============================================================
// Phase 2: persistent recurrence, ONE barrier per step.
// CTA c owns h-columns j0..j0+3 and gate rows {q*512 + j0 + r}
// (q=0..3 gates, r=0..3) -> cell update is intra-CTA.
// ============================================================
extern __shared__ __align__(16) float smem_rec[];

__global__ void __launch_bounds__(256) lstm_rec(
    const float* __restrict__ Wh, float* __restrict__ out)
{
    float* ws = smem_rec;                     // [16][512] weights
    float* hs = smem_rec + 16 * HDIM;         // [32][HSTRIDE] h staging

    __shared__ float sact[16][32];            // activated gates [rr][b]
    __shared__ float houts[32][4];            // new h [b][jl] for coalesced out
    __shared__ unsigned long long sbase;

    const int tid  = threadIdx.x;
    const int cta  = blockIdx.x;
    const int j0   = cta * 4;
    const int warp = tid >> 5;
    const int lane = tid & 31;

    // Load 16 Wh rows: rr = q*4+r -> global row q*512 + j0 + r
    #pragma unroll
    for (int r8 = 0; r8 < 8; r8++) {
        int f4 = r8 * 256 + tid;          // 2048 float4 total
        int rr = f4 >> 7;
        int kc = f4 & 127;
        int grow = (rr >> 2) * HDIM + j0 + (rr & 3);
        *(float4*)(ws + rr * HDIM + kc * 4) =
            *(const float4*)(Wh + (size_t)grow * HDIM + kc * 4);
    }

    // cell ownership: threads 0..127 own (jl = tid>>5, b = tid&31)
    const int ub  = tid & 31;
    const int ujl = tid >> 5;
    float creg = 0.f;
    if (tid < 128) g_h[0][ub * HDIM + j0 + ujl] = 0.f;

    if (tid == 0) {
        unsigned long long v = *(volatile unsigned long long*)&g_cnt;
        unsigned long long per = (unsigned long long)NBAR * RG;
        sbase = (v / per) * per;
    }
    __syncthreads();
    const unsigned long long base = sbase;
    int bar = 0;
    gbar(base, ++bar);     // h buffer 0 initialized everywhere

    // matvec roles: warp handles rr0 = 2*warp, rr1 = 2*warp+1; lane = b
    const int rr0 = 2 * warp, rr1 = rr0 + 1;
    const int gg0 = (rr0 >> 2) * HDIM + j0 + (rr0 & 3);
    const int gg1 = (rr1 >> 2) * HDIM + j0 + (rr1 & 3);
    const ulonglong2* w0p = (const ulonglong2*)(ws + rr0 * HDIM);
    const ulonglong2* w1p = (const ulonglong2*)(ws + rr1 * HDIM);
    const bool tanh0 = (rr0 >= 12), tanh1 = (rr1 >= 12);

    for (int t = 0; t < TSTEPS; t++) {
        const int p = t & 1;
        // prefetch x_pre (hide L2/DRAM latency behind staging)
        const float* xp = g_xpre + (size_t)t * GDIM * BATCH;
        float x0 = __ldg(xp + (size_t)gg0 * BATCH + lane);
        float x1 = __ldg(xp + (size_t)gg1 * BATCH + lane);

        // stage h: 4096 float4 over 256 threads
        const float4* hsrc = (const float4*)g_h[p];
        #pragma unroll
        for (int r = 0; r < 16; r++) {
            int f4 = r * 256 + tid;
            int b  = f4 >> 7;
            int c4 = f4 & 127;
            float4 v = __ldcg(hsrc + f4);
            *(float4*)(hs + b * HSTRIDE + c4 * 4) = v;
        }
        __syncthreads();

        // dot products: 2 gate rows x 32 b per warp (f32x2)
        const ulonglong2* hp = (const ulonglong2*)(hs + lane * HSTRIDE);
        unsigned long long a0x = 0, a0y = 0, a1x = 0, a1y = 0;
        #pragma unroll 8
        for (int k4 = 0; k4 < 128; k4++) {
            ulonglong2 hv = hp[k4];
            ulonglong2 wa = w0p[k4];
            ulonglong2 wb = w1p[k4];
            a0x = fma2(wa.x, hv.x, a0x);
            a0y = fma2(wa.y, hv.y, a0y);
            a1x = fma2(wb.x, hv.x, a1x);
            a1y = fma2(wb.y, hv.y, a1y);
        }
        float p0 = hsum2(fma2(a0x, 0x3F8000003F800000ULL, a0y)) + x0; // a0x*1 + a0y
        float p1 = hsum2(fma2(a1x, 0x3F8000003F800000ULL, a1y)) + x1;
        float a0 = tanh0 ? tanhf(p0) : (1.f / (1.f + __expf(-p0)));
        float a1 = tanh1 ? tanhf(p1) : (1.f / (1.f + __expf(-p1)));
        sact[rr0][lane] = a0;
        sact[rr1][lane] = a1;
        __syncthreads();

        // intra-CTA cell update (threads 0..127)
        if (tid < 128) {
            float ig = sact[0 * 4 + ujl][ub];
            float fg = sact[1 * 4 + ujl][ub];
            float og = sact[2 * 4 + ujl][ub];
            float gt = sact[3 * 4 + ujl][ub];
            creg = creg * fg + ig * gt;
            float hn = og * tanhf(creg);
            g_h[p ^ 1][ub * HDIM + j0 + ujl] = hn;
            houts[ub][ujl] = hn;
            if (t == TSTEPS - 1) {
                size_t o2 = (size_t)TSTEPS * BATCH * HDIM;
                out[o2 + ub * HDIM + j0 + ujl] = hn;
                out[o2 + BATCH * HDIM + ub * HDIM + j0 + ujl] = creg;
            }
        }

        gbar(base, ++bar);    // h(t+1) visible everywhere

        // coalesced output write for step t (float4 per (t,b)); houts is
        // stable until the next cell update, which is 2 syncs away.
        if (tid < 32)
            *(float4*)(out + ((size_t)t * BATCH + tid) * HDIM + j0) =
                *(const float4*)houts[tid];
    }
}

// ============================================================
extern "C" void kernel_launch(void* const* d_in, const int* in_sizes, int n_in,
                              void* d_out, int out_size)
{
    const float* x  = (const float*)d_in[0];
    const float* Wi = (const float*)d_in[1];
    const float* bi = (const float*)d_in[2];
    const float* Wh = (const float*)d_in[3];
    const float* bh = (const float*)d_in[4];
    float* out = (float*)d_out;

    size_t rec_smem = (size_t)(16 * HDIM + BATCH * HSTRIDE) * sizeof(float); // 98816 B
    cudaFuncSetAttribute(lstm_rec, cudaFuncAttributeMaxDynamicSharedMemorySize,
                         (int)rec_smem);

    dim3 g1(GDIM / 128, TSTEPS);
    p1_gemm<<<g1, 256>>>(x, Wi, bi, bh);
    lstm_rec<<<RG, 256, rec_smem>>>(Wh, out);
}

// round 4
// speedup vs baseline: 1.7142x; 1.4009x over previous
#include <cuda_runtime.h>
#include <cstdint>

#define TSTEPS 2048
#define BATCH  32
#define IDIM   512
#define HDIM   512
#define GDIM   2048   // 4*H

#define RG      128    // persistent CTAs in recurrence
#define HSTRIDE 516    // padded h row stride in smem (floats); 516 % 32 == 4
#define SREDST  33     // sred b-stride
#define NBAR    (1 + TSTEPS)

// ---- static device scratch (no cudaMalloc allowed) ----
__device__ float g_xpre[(size_t)TSTEPS * GDIM * BATCH];   // [t][g][b]
__device__ float g_h[2][BATCH * HDIM];                    // double-buffered h
__device__ unsigned long long g_cnt;                      // grid barrier counter

// ---- packed fp32x2 helpers (phase 1) ----
__device__ __forceinline__ unsigned long long fma2(
    unsigned long long a, unsigned long long b, unsigned long long c)
{
    unsigned long long d;
    asm("fma.rn.f32x2 %0, %1, %2, %3;" : "=l"(d) : "l"(a), "l"(b), "l"(c));
    return d;
}
__device__ __forceinline__ float hsum2(unsigned long long p)
{
    float lo, hi;
    asm("mov.b64 {%0, %1}, %2;" : "=f"(lo), "=f"(hi) : "l"(p));
    return lo + hi;
}

// ---- tf32 mma helper: D += A(16x8) * B(8x8), fp32 accum ----
__device__ __forceinline__ void mma_tf32(float (&d)[4], const unsigned (&a)[4],
                                         unsigned b0, unsigned b1)
{
    asm("mma.sync.aligned.m16n8k8.row.col.f32.tf32.tf32.f32 "
        "{%0,%1,%2,%3}, {%4,%5,%6,%7}, {%8,%9}, {%0,%1,%2,%3};"
        : "+f"(d[0]), "+f"(d[1]), "+f"(d[2]), "+f"(d[3])
        : "r"(a[0]), "r"(a[1]), "r"(a[2]), "r"(a[3]), "r"(b0), "r"(b1));
}

// ============================================================
// Phase 1: x_pre[t][g][b] = (bi[g]+bh[g]) + sum_i Wi[g][i]*x[t][b][i]
// (unchanged from round 3 — f32x2 inner product)
// ============================================================
__global__ void __launch_bounds__(256) p1_gemm(
    const float* __restrict__ x, const float* __restrict__ Wi,
    const float* __restrict__ bi, const float* __restrict__ bh)
{
    __shared__ __align__(16) float wt[128 * 32];
    __shared__ __align__(16) float xt[32 * 32];

    const int t     = blockIdx.y;
    const int gbase = blockIdx.x * 128;
    const int tid   = threadIdx.x;
    const int tx    = tid & 7;
    const int ty    = tid >> 3;

    unsigned long long acc[4][4];
    #pragma unroll
    for (int i = 0; i < 4; i++)
        #pragma unroll
        for (int j = 0; j < 4; j++) acc[i][j] = 0ULL;

    const float* xrow = x + (size_t)t * BATCH * IDIM;
    const int sb = tid >> 3;
    const int sc = tid & 7;

    ulonglong2* xt2 = (ulonglong2*)xt;
    ulonglong2* wt2 = (ulonglong2*)wt;

    for (int kb = 0; kb < IDIM; kb += 32) {
        __syncthreads();
        #pragma unroll
        for (int r = 0; r < 4; r++) {
            int idx = r * 256 + tid;
            int g   = idx >> 3;
            int c   = idx & 7;
            float4 v = *(const float4*)(Wi + (size_t)(gbase + g) * IDIM + kb + c * 4);
            *(float4*)(wt + (g * 8 + c) * 4) = v;
        }
        {
            float4 v = *(const float4*)(xrow + (size_t)sb * IDIM + kb + sc * 4);
            *(float4*)(xt + (sb * 8 + (sc ^ (sb & 7))) * 4) = v;
        }
        __syncthreads();

        #pragma unroll
        for (int c = 0; c < 8; c++) {
            ulonglong2 xv[4], wv[4];
            #pragma unroll
            for (int j = 0; j < 4; j++) {
                int b = tx + 8 * j;
                xv[j] = xt2[b * 8 + (c ^ tx)];
            }
            #pragma unroll
            for (int i = 0; i < 4; i++)
                wv[i] = wt2[(ty * 4 + i) * 8 + c];
            #pragma unroll
            for (int i = 0; i < 4; i++)
                #pragma unroll
                for (int j = 0; j < 4; j++) {
                    acc[i][j] = fma2(wv[i].x, xv[j].x, acc[i][j]);
                    acc[i][j] = fma2(wv[i].y, xv[j].y, acc[i][j]);
                }
        }
    }

    float* outp = g_xpre + (size_t)t * GDIM * BATCH;
    #pragma unroll
    for (int i = 0; i < 4; i++) {
        int g = gbase + ty * 4 + i;
        float bb = __ldg(bi + g) + __ldg(bh + g);
        #pragma unroll
        for (int j = 0; j < 4; j++) {
            int b = tx + 8 * j;
            outp[(size_t)g * BATCH + b] = hsum2(acc[i][j]) + bb;
        }
    }
}

// ============================================================
// Grid barrier: monotone u64 counter (graph-replay safe)
// ============================================================
__device__ __forceinline__ void gbar(unsigned long long base, int bar)
{
    __syncthreads();
    if (threadIdx.x == 0) {
        __threadfence();
        atomicAdd(&g_cnt, 1ULL);
        unsigned long long target = base + (unsigned long long)bar * RG;
        volatile unsigned long long* vc = &g_cnt;
        while (*vc < target) __nanosleep(16);
        __threadfence();
    }
    __syncthreads();
}

// ============================================================
// Phase 2: persistent recurrence via split-tf32 tensor cores.
// CTA c owns h-cols j0..j0+3 <-> 16 gate rows rr=q*4+r -> q*512+j0+r.
// 8 warps k-split (64 k each); Wh A-frags pre-split hi/lo in REGISTERS.
// G = Whi*Bhi + Wlo*Bhi + Whi*Blo  (fp32-grade accuracy).
// ============================================================
extern __shared__ __align__(16) float hs[];     // [32][HSTRIDE] h staging (fp32)

__global__ void __launch_bounds__(256) lstm_rec(
    const float* __restrict__ Wh, float* __restrict__ out)
{
    __shared__ float sred[8 * 16 * SREDST];     // per-warp partials [w][rr][b]
    __shared__ float houts[32][4];
    __shared__ unsigned long long sbase;

    const int tid  = threadIdx.x;
    const int cta  = blockIdx.x;
    const int j0   = cta * 4;
    const int warp = tid >> 5;
    const int lane = tid & 31;
    const int gid  = lane >> 2;   // 0..7
    const int tid4 = lane & 3;    // 0..3

    // ---- preload Wh A-fragments, split into tf32 hi/lo (regs, loop-invariant)
    unsigned whi[8][4], wlo[8][4];
    {
        const int r0 = gid, r1 = gid + 8;
        const int grow0 = (r0 >> 2) * HDIM + j0 + (r0 & 3);
        const int grow1 = (r1 >> 2) * HDIM + j0 + (r1 & 3);
        const int kbase = warp * 64;
        #pragma unroll
        for (int c = 0; c < 8; c++) {
            int k0 = kbase + c * 8 + tid4;
            float a[4];
            a[0] = Wh[(size_t)grow0 * HDIM + k0];
            a[1] = Wh[(size_t)grow1 * HDIM + k0];
            a[2] = Wh[(size_t)grow0 * HDIM + k0 + 4];
            a[3] = Wh[(size_t)grow1 * HDIM + k0 + 4];
            #pragma unroll
            for (int i = 0; i < 4; i++) {
                unsigned hb = __float_as_uint(a[i]) & 0xFFFFE000u;
                whi[c][i] = hb;
                wlo[c][i] = __float_as_uint(a[i] - __uint_as_float(hb));
            }
        }
    }

    // cell ownership: threads 0..127 own (jl = tid>>5, b = tid&31)
    const int ub  = tid & 31;
    const int ujl = tid >> 5;
    float creg = 0.f;
    if (tid < 128) g_h[0][ub * HDIM + j0 + ujl] = 0.f;

    if (tid == 0) {
        unsigned long long v = *(volatile unsigned long long*)&g_cnt;
        unsigned long long per = (unsigned long long)NBAR * RG;
        sbase = (v / per) * per;
    }
    __syncthreads();
    const unsigned long long base = sbase;
    int bar = 0;
    gbar(base, ++bar);     // h buffer 0 initialized everywhere

    const int kb4 = warp * 64 + tid4;

    for (int t = 0; t < TSTEPS; t++) {
        const int p = t & 1;

        // prefetch x_pre for the cell phase (hide DRAM latency)
        float xq[4];
        if (tid < 128) {
            #pragma unroll
            for (int q = 0; q < 4; q++)
                xq[q] = __ldg(g_xpre + ((size_t)t * GDIM + q * HDIM + j0 + ujl) * BATCH + ub);
        }

        // stage h: 4096 float4 over 256 threads, [b][k] stride HSTRIDE
        const float4* hsrc = (const float4*)g_h[p];
        #pragma unroll
        for (int r = 0; r < 16; r++) {
            int f4 = r * 256 + tid;
            int b  = f4 >> 7;
            int c4 = f4 & 127;
            float4 v = __ldcg(hsrc + f4);
            *(float4*)(hs + b * HSTRIDE + c4 * 4) = v;
        }
        __syncthreads();

        // ---- tensor-core matvec: per warp 8 k-chunks x 4 n-tiles, 3 mma each
        float acc[4][4];
        #pragma unroll
        for (int nt = 0; nt < 4; nt++)
            #pragma unroll
            for (int i = 0; i < 4; i++) acc[nt][i] = 0.f;

        #pragma unroll
        for (int c = 0; c < 8; c++) {
            int k0 = kb4 + c * 8;
            #pragma unroll
            for (int nt = 0; nt < 4; nt++) {
                int b = nt * 8 + gid;
                float f0 = hs[b * HSTRIDE + k0];
                float f1 = hs[b * HSTRIDE + k0 + 4];
                unsigned bh0 = __float_as_uint(f0) & 0xFFFFE000u;
                unsigned bh1 = __float_as_uint(f1) & 0xFFFFE000u;
                unsigned bl0 = __float_as_uint(f0 - __uint_as_float(bh0));
                unsigned bl1 = __float_as_uint(f1 - __uint_as_float(bh1));
                mma_tf32(acc[nt], whi[c], bh0, bh1);
                mma_tf32(acc[nt], wlo[c], bh0, bh1);
                mma_tf32(acc[nt], whi[c], bl0, bl1);
            }
        }

        // ---- spill per-warp partials: C-frag mapping
        // c0:(gid, 2*tid4) c1:(gid, 2*tid4+1) c2:(gid+8, ...) c3:(gid+8, ...+1)
        {
            float* sr = sred + warp * 16 * SREDST;
            #pragma unroll
            for (int nt = 0; nt < 4; nt++) {
                int bb = nt * 8 + 2 * tid4;
                sr[gid * SREDST + bb]           = acc[nt][0];
                sr[gid * SREDST + bb + 1]       = acc[nt][1];
                sr[(gid + 8) * SREDST + bb]     = acc[nt][2];
                sr[(gid + 8) * SREDST + bb + 1] = acc[nt][3];
            }
        }
        __syncthreads();

        // ---- reduce 8 warps + x_pre, activation, cell update (threads 0..127)
        if (tid < 128) {
            float pre[4];
            #pragma unroll
            for (int q = 0; q < 4; q++) {
                int rr = q * 4 + ujl;
                float s = xq[q];
                #pragma unroll
                for (int w = 0; w < 8; w++)
                    s += sred[(w * 16 + rr) * SREDST + ub];
                pre[q] = s;
            }
            float ig = 1.f / (1.f + __expf(-pre[0]));
            float fg = 1.f / (1.f + __expf(-pre[1]));
            float og = 1.f / (1.f + __expf(-pre[2]));
            float gt = tanhf(pre[3]);
            creg = creg * fg + ig * gt;
            float hn = og * tanhf(creg);
            g_h[p ^ 1][ub * HDIM + j0 + ujl] = hn;
            houts[ub][ujl] = hn;
            if (t == TSTEPS - 1) {
                size_t o2 = (size_t)TSTEPS * BATCH * HDIM;
                out[o2 + ub * HDIM + j0 + ujl] = hn;
                out[o2 + BATCH * HDIM + ub * HDIM + j0 + ujl] = creg;
            }
        }

        gbar(base, ++bar);    // h(t+1) visible everywhere

        // coalesced output write for step t; houts stable until next cell phase
        if (tid < 32)
            *(float4*)(out + ((size_t)t * BATCH + tid) * HDIM + j0) =
                *(const float4*)houts[tid];
    }
}

// ============================================================
extern "C" void kernel_launch(void* const* d_in, const int* in_sizes, int n_in,
                              void* d_out, int out_size)
{
    const float* x  = (const float*)d_in[0];
    const float* Wi = (const float*)d_in[1];
    const float* bi = (const float*)d_in[2];
    const float* Wh = (const float*)d_in[3];
    const float* bh = (const float*)d_in[4];
    float* out = (float*)d_out;

    size_t rec_smem = (size_t)(BATCH * HSTRIDE) * sizeof(float); // 66048 B
    cudaFuncSetAttribute(lstm_rec, cudaFuncAttributeMaxDynamicSharedMemorySize,
                         (int)rec_smem);

    dim3 g1(GDIM / 128, TSTEPS);
    p1_gemm<<<g1, 256>>>(x, Wi, bi, bh);
    lstm_rec<<<RG, 256, rec_smem>>>(Wh, out);
}

// round 5
// speedup vs baseline: 2.1951x; 1.2805x over previous
#include <cuda_runtime.h>
#include <cuda_bf16.h>
#include <cstdint>

#define TSTEPS 2048
#define BATCH  32
#define IDIM   512
#define HDIM   512
#define GDIM   2048   // 4*H

#define RG      128    // persistent CTAs in recurrence
#define HSTRIDE 516    // padded h row stride in smem (floats)
#define SREDST  33     // sred b-stride
#define NBAR    (1 + TSTEPS)

#define TOTX (TSTEPS * BATCH * IDIM)   // 33,554,432
#define TOTW (GDIM * IDIM)             // 1,048,576

// ---- static device scratch (no cudaMalloc allowed) ----
__device__ float g_xpre[(size_t)TSTEPS * GDIM * BATCH];   // [t][g][b]
__device__ float g_h[2][BATCH * HDIM];                    // double-buffered h
__device__ unsigned long long g_cnt;                      // grid barrier counter
// bf16 hi/lo split planes (uint4 for 16B alignment)
__device__ uint4 g_xhi4[TOTX / 8], g_xlo4[TOTX / 8];      // [t][b][k] bf16
__device__ uint4 g_whi4[TOTW / 8], g_wlo4[TOTW / 8];      // [g][k]    bf16

// ---- mma helpers ----
__device__ __forceinline__ void mma_tf32(float (&d)[4], const unsigned (&a)[4],
                                         unsigned b0, unsigned b1)
{
    asm("mma.sync.aligned.m16n8k8.row.col.f32.tf32.tf32.f32 "
        "{%0,%1,%2,%3}, {%4,%5,%6,%7}, {%8,%9}, {%0,%1,%2,%3};"
        : "+f"(d[0]), "+f"(d[1]), "+f"(d[2]), "+f"(d[3])
        : "r"(a[0]), "r"(a[1]), "r"(a[2]), "r"(a[3]), "r"(b0), "r"(b1));
}
__device__ __forceinline__ void mma_bf16(float (&d)[4], const unsigned (&a)[4],
                                         unsigned b0, unsigned b1)
{
    asm("mma.sync.aligned.m16n8k16.row.col.f32.bf16.bf16.f32 "
        "{%0,%1,%2,%3}, {%4,%5,%6,%7}, {%8,%9}, {%0,%1,%2,%3};"
        : "+f"(d[0]), "+f"(d[1]), "+f"(d[2]), "+f"(d[3])
        : "r"(a[0]), "r"(a[1]), "r"(a[2]), "r"(a[3]), "r"(b0), "r"(b1));
}

// ============================================================
// Prep: split fp32 -> bf16 hi/lo planes
// ============================================================
__global__ void __launch_bounds__(256) split_x(const float* __restrict__ x)
{
    int i = blockIdx.x * 256 + threadIdx.x;   // TOTX threads
    __nv_bfloat16* hp = (__nv_bfloat16*)g_xhi4;
    __nv_bfloat16* lp = (__nv_bfloat16*)g_xlo4;
    float v = x[i];
    __nv_bfloat16 h = __float2bfloat16(v);
    hp[i] = h;
    lp[i] = __float2bfloat16(v - __bfloat162float(h));
}
__global__ void __launch_bounds__(256) split_wi(const float* __restrict__ W)
{
    int i = blockIdx.x * 256 + threadIdx.x;   // TOTW threads
    __nv_bfloat16* hp = (__nv_bfloat16*)g_whi4;
    __nv_bfloat16* lp = (__nv_bfloat16*)g_wlo4;
    float v = W[i];
    __nv_bfloat16 h = __float2bfloat16(v);
    hp[i] = h;
    lp[i] = __float2bfloat16(v - __bfloat162float(h));
}

// ============================================================
// Phase 1 (bf16 split-MMA): x_pre[t][g][b] = (bi+bh)[g] + Wi[g,:]·x[t,b,:]
// CTA: 128 g x 32 b for one t; 8 warps each own 16 g-rows.
// smem planes padded to word-stride 36 -> bank (4g+t): conflict-free.
// ============================================================
__global__ void __launch_bounds__(256, 2) p1_gemm(
    const float* __restrict__ bi, const float* __restrict__ bh)
{
    __shared__ __align__(16) unsigned sw[2][128 * 36];  // Wi hi/lo, 36 words/row
    __shared__ __align__(16) unsigned sx[2][32 * 36];   // x  hi/lo

    const int t     = blockIdx.y;
    const int gbase = blockIdx.x * 128;
    const int tid   = threadIdx.x;
    const int wid   = tid >> 5;
    const int lane  = tid & 31;
    const int g     = lane >> 2;   // 0..7
    const int t4    = lane & 3;    // 0..3

    float acc[4][4];
    #pragma unroll
    for (int nt = 0; nt < 4; nt++)
        #pragma unroll
        for (int i = 0; i < 4; i++) acc[nt][i] = 0.f;

    const uint4* xsrc_h = g_xhi4 + ((size_t)t * BATCH * IDIM) / 8;
    const uint4* xsrc_l = g_xlo4 + ((size_t)t * BATCH * IDIM) / 8;

    for (int kb = 0; kb < IDIM; kb += 64) {
        __syncthreads();
        // stage Wi planes: 1024 16B chunks each (4/thread)
        #pragma unroll
        for (int r = 0; r < 4; r++) {
            int ch  = r * 256 + tid;
            int row = ch >> 3, c8 = ch & 7;
            size_t src = ((size_t)(gbase + row) * IDIM + kb) / 8 + c8;
            ((uint4*)sw[0])[row * 9 + c8] = g_whi4[src];
            ((uint4*)sw[1])[row * 9 + c8] = g_wlo4[src];
        }
        // stage x planes: 256 chunks each (1/thread)
        {
            int row = tid >> 3, c8 = tid & 7;
            size_t src = ((size_t)row * IDIM + kb) / 8 + c8;
            ((uint4*)sx[0])[row * 9 + c8] = xsrc_h[src];
            ((uint4*)sx[1])[row * 9 + c8] = xsrc_l[src];
        }
        __syncthreads();

        #pragma unroll
        for (int c = 0; c < 4; c++) {       // 4 k16 chunks in this 64-block
            const int aw = (wid * 16 + g) * 36 + c * 8 + t4;
            unsigned ahi[4], alo[4];
            ahi[0] = sw[0][aw];            ahi[1] = sw[0][aw + 8 * 36];
            ahi[2] = sw[0][aw + 4];        ahi[3] = sw[0][aw + 8 * 36 + 4];
            alo[0] = sw[1][aw];            alo[1] = sw[1][aw + 8 * 36];
            alo[2] = sw[1][aw + 4];        alo[3] = sw[1][aw + 8 * 36 + 4];
            #pragma unroll
            for (int nt = 0; nt < 4; nt++) {
                const int bw = (nt * 8 + g) * 36 + c * 8 + t4;
                unsigned bh0 = sx[0][bw], bh1 = sx[0][bw + 4];
                unsigned bl0 = sx[1][bw], bl1 = sx[1][bw + 4];
                mma_bf16(acc[nt], ahi, bh0, bh1);
                mma_bf16(acc[nt], alo, bh0, bh1);
                mma_bf16(acc[nt], ahi, bl0, bl1);
            }
        }
    }

    // epilogue: C rows (g, g+8), cols 2t4, 2t4+1 within each n-tile
    const int grow0 = gbase + wid * 16 + g;
    const int grow1 = grow0 + 8;
    const float bb0 = __ldg(bi + grow0) + __ldg(bh + grow0);
    const float bb1 = __ldg(bi + grow1) + __ldg(bh + grow1);
    float* op = g_xpre + (size_t)t * GDIM * BATCH;
    #pragma unroll
    for (int nt = 0; nt < 4; nt++) {
        int b = nt * 8 + 2 * t4;
        *(float2*)(op + (size_t)grow0 * BATCH + b) =
            make_float2(acc[nt][0] + bb0, acc[nt][1] + bb0);
        *(float2*)(op + (size_t)grow1 * BATCH + b) =
            make_float2(acc[nt][2] + bb1, acc[nt][3] + bb1);
    }
}

// ============================================================
// Grid barrier: release-arrive + acquire-spin (no MEMBAR.GPU)
// ============================================================
__device__ __forceinline__ void gbar(unsigned long long base, int bar)
{
    __syncthreads();
    if (threadIdx.x == 0) {
        unsigned long long target = base + (unsigned long long)bar * RG;
        unsigned long long* p = &g_cnt;
        asm volatile("red.release.gpu.add.u64 [%0], %1;"
                     :: "l"(p), "l"(1ULL) : "memory");
        unsigned long long v;
        do {
            asm volatile("ld.acquire.gpu.b64 %0, [%1];"
                         : "=l"(v) : "l"(p) : "memory");
        } while (v < target);
    }
    __syncthreads();
}

// ============================================================
// Phase 2: persistent recurrence via split-tf32 tensor cores.
// (structure as round 4; barrier + reduce tweaks)
// ============================================================
extern __shared__ __align__(16) float hs[];     // [32][HSTRIDE] h staging

__global__ void __launch_bounds__(256) lstm_rec(
    const float* __restrict__ Wh, float* __restrict__ out)
{
    __shared__ float sred[8 * 16 * SREDST];     // per-warp partials [w][rr][b]
    __shared__ float houts[32][4];
    __shared__ unsigned long long sbase;

    const int tid  = threadIdx.x;
    const int cta  = blockIdx.x;
    const int j0   = cta * 4;
    const int warp = tid >> 5;
    const int lane = tid & 31;
    const int gid  = lane >> 2;
    const int tid4 = lane & 3;

    // preload Wh A-fragments, split tf32 hi/lo in registers
    unsigned whi[8][4], wlo[8][4];
    {
        const int r0 = gid, r1 = gid + 8;
        const int grow0 = (r0 >> 2) * HDIM + j0 + (r0 & 3);
        const int grow1 = (r1 >> 2) * HDIM + j0 + (r1 & 3);
        const int kbase = warp * 64;
        #pragma unroll
        for (int c = 0; c < 8; c++) {
            int k0 = kbase + c * 8 + tid4;
            float a[4];
            a[0] = Wh[(size_t)grow0 * HDIM + k0];
            a[1] = Wh[(size_t)grow1 * HDIM + k0];
            a[2] = Wh[(size_t)grow0 * HDIM + k0 + 4];
            a[3] = Wh[(size_t)grow1 * HDIM + k0 + 4];
            #pragma unroll
            for (int i = 0; i < 4; i++) {
                unsigned hb = __float_as_uint(a[i]) & 0xFFFFE000u;
                whi[c][i] = hb;
                wlo[c][i] = __float_as_uint(a[i] - __uint_as_float(hb));
            }
        }
    }

    const int ub  = tid & 31;
    const int ujl = tid >> 5;
    float creg = 0.f;
    if (tid < 128) g_h[0][ub * HDIM + j0 + ujl] = 0.f;

    if (tid == 0) {
        unsigned long long v = *(volatile unsigned long long*)&g_cnt;
        unsigned long long per = (unsigned long long)NBAR * RG;
        sbase = (v / per) * per;
    }
    __syncthreads();
    const unsigned long long base = sbase;
    int bar = 0;
    gbar(base, ++bar);

    const int kb4 = warp * 64 + tid4;

    for (int t = 0; t < TSTEPS; t++) {
        const int p = t & 1;

        float xq[4];
        if (tid < 128) {
            #pragma unroll
            for (int q = 0; q < 4; q++)
                xq[q] = __ldg(g_xpre + ((size_t)t * GDIM + q * HDIM + j0 + ujl) * BATCH + ub);
        }

        const float4* hsrc = (const float4*)g_h[p];
        #pragma unroll
        for (int r = 0; r < 16; r++) {
            int f4 = r * 256 + tid;
            int b  = f4 >> 7;
            int c4 = f4 & 127;
            float4 v = __ldcg(hsrc + f4);
            *(float4*)(hs + b * HSTRIDE + c4 * 4) = v;
        }
        __syncthreads();

        float acc[4][4];
        #pragma unroll
        for (int nt = 0; nt < 4; nt++)
            #pragma unroll
            for (int i = 0; i < 4; i++) acc[nt][i] = 0.f;

        #pragma unroll
        for (int c = 0; c < 8; c++) {
            int k0 = kb4 + c * 8;
            #pragma unroll
            for (int nt = 0; nt < 4; nt++) {
                int b = nt * 8 + gid;
                float f0 = hs[b * HSTRIDE + k0];
                float f1 = hs[b * HSTRIDE + k0 + 4];
                unsigned bh0 = __float_as_uint(f0) & 0xFFFFE000u;
                unsigned bh1 = __float_as_uint(f1) & 0xFFFFE000u;
                unsigned bl0 = __float_as_uint(f0 - __uint_as_float(bh0));
                unsigned bl1 = __float_as_uint(f1 - __uint_as_float(bh1));
                mma_tf32(acc[nt], whi[c], bh0, bh1);
                mma_tf32(acc[nt], wlo[c], bh0, bh1);
                mma_tf32(acc[nt], whi[c], bl0, bl1);
            }
        }

        {
            float* sr = sred + warp * 16 * SREDST;
            #pragma unroll
            for (int nt = 0; nt < 4; nt++) {
                int bb = nt * 8 + 2 * tid4;
                sr[gid * SREDST + bb]           = acc[nt][0];
                sr[gid * SREDST + bb + 1]       = acc[nt][1];
                sr[(gid + 8) * SREDST + bb]     = acc[nt][2];
                sr[(gid + 8) * SREDST + bb + 1] = acc[nt][3];
            }
        }
        __syncthreads();

        if (tid < 128) {
            float pre[4];
            #pragma unroll
            for (int q = 0; q < 4; q++) {
                int rr = q * 4 + ujl;
                float v0 = sred[(0 * 16 + rr) * SREDST + ub];
                float v1 = sred[(1 * 16 + rr) * SREDST + ub];
                float v2 = sred[(2 * 16 + rr) * SREDST + ub];
                float v3 = sred[(3 * 16 + rr) * SREDST + ub];
                float v4 = sred[(4 * 16 + rr) * SREDST + ub];
                float v5 = sred[(5 * 16 + rr) * SREDST + ub];
                float v6 = sred[(6 * 16 + rr) * SREDST + ub];
                float v7 = sred[(7 * 16 + rr) * SREDST + ub];
                pre[q] = ((v0 + v1) + (v2 + v3)) + ((v4 + v5) + (v6 + v7)) + xq[q];
            }
            float ig = 1.f / (1.f + __expf(-pre[0]));
            float fg = 1.f / (1.f + __expf(-pre[1]));
            float og = 1.f / (1.f + __expf(-pre[2]));
            float gt = tanhf(pre[3]);
            creg = creg * fg + ig * gt;
            float hn = og * tanhf(creg);
            g_h[p ^ 1][ub * HDIM + j0 + ujl] = hn;
            houts[ub][ujl] = hn;
            if (t == TSTEPS - 1) {
                size_t o2 = (size_t)TSTEPS * BATCH * HDIM;
                out[o2 + ub * HDIM + j0 + ujl] = hn;
                out[o2 + BATCH * HDIM + ub * HDIM + j0 + ujl] = creg;
            }
        }

        gbar(base, ++bar);

        if (tid < 32)
            *(float4*)(out + ((size_t)t * BATCH + tid) * HDIM + j0) =
                *(const float4*)houts[tid];
    }
}

// ============================================================
extern "C" void kernel_launch(void* const* d_in, const int* in_sizes, int n_in,
                              void* d_out, int out_size)
{
    const float* x  = (const float*)d_in[0];
    const float* Wi = (const float*)d_in[1];
    const float* bi = (const float*)d_in[2];
    const float* Wh = (const float*)d_in[3];
    const float* bh = (const float*)d_in[4];
    float* out = (float*)d_out;

    size_t rec_smem = (size_t)(BATCH * HSTRIDE) * sizeof(float); // 66048 B
    cudaFuncSetAttribute(lstm_rec, cudaFuncAttributeMaxDynamicSharedMemorySize,
                         (int)rec_smem);

    split_x<<<TOTX / 256, 256>>>(x);
    split_wi<<<TOTW / 256, 256>>>(Wi);
    dim3 g1(GDIM / 128, TSTEPS);
    p1_gemm<<<g1, 256>>>(bi, bh);
    lstm_rec<<<RG, 256, rec_smem>>>(Wh, out);
}